// round 1
// baseline (speedup 1.0000x reference)
#include <cuda_runtime.h>
#include <cuda_bf16.h>
#include <math.h>

// ---------------------------------------------------------------------------
// Problem: 3x exact top-K selection over columns of A (N x 2), indices sorted
// by (value desc, index asc) to match lax.top_k; gather h rows; 512->2 GEMV;
// softmax(2). Output layout (float32, 15*K elems):
//   [0, 3K)        labels: 1.0 for r<K else 0.0
//   [3K, 9K)       logits_unnorm, row-major (3K rows x 2)
//   [9K, 15K)      softmax probs,  row-major (3K rows x 2)
// ---------------------------------------------------------------------------

#define SEL_BLOCK 1024
#define SORT_M    2048   // next pow2 >= K (K=2000 for N=100000)

__device__ int g_idx[3 * SORT_M];   // selected indices, sorted, per selection

__device__ __forceinline__ unsigned fkey(float f) {
    unsigned u = __float_as_uint(f);
    // monotonic mapping: larger float -> larger unsigned
    return (u & 0x80000000u) ? ~u : (u | 0x80000000u);
}

// Build 64-bit key: high 32 = monotonic float key, low 32 = ~index.
// Descending sort on key64 == (value desc, index asc). Keys are unique.
__device__ __forceinline__ unsigned long long make_key(const float* __restrict__ A,
                                                       int i, int col, bool negate) {
    float v = A[(size_t)i * 2 + col];
    if (negate) v = -v;
    return ((unsigned long long)fkey(v) << 32) | (unsigned)(~(unsigned)i);
}

// One block per selection: exact radix-select of K-th largest 64-bit key,
// then compact + bitonic sort the K winners, write sorted indices.
__global__ __launch_bounds__(SEL_BLOCK)
void select_topk_kernel(const float* __restrict__ A, const int* __restrict__ bag,
                        int N, int K) {
    const int sel = blockIdx.x;          // 0: top A[:,bag]  1: top -A[:,bag]  2: top A[:,1-bag]
    const int tid = threadIdx.x;
    const int lane = tid & 31;

    int bg = bag ? *bag : 1;
    const int col    = (sel == 2) ? (1 - bg) : bg;
    const bool neg   = (sel == 1);

    __shared__ unsigned hist[256];
    __shared__ unsigned long long s_pref;
    __shared__ int s_k;
    __shared__ int s_cnt;
    __shared__ unsigned long long keys[SORT_M];

    if (tid == 0) { s_pref = 0ull; s_k = K; }
    __syncthreads();

    const int Npad = ((N + SEL_BLOCK - 1) / SEL_BLOCK) * SEL_BLOCK;

    // ---- 8-pass MSB-first radix select over 64-bit keys ----
    for (int byte = 7; byte >= 0; --byte) {
        for (int bkt = tid; bkt < 256; bkt += SEL_BLOCK) hist[bkt] = 0;
        __syncthreads();

        const unsigned long long pref  = s_pref;
        const unsigned long long hmask = (byte == 7) ? 0ull : (~0ull << ((byte + 1) * 8));
        const int shift = byte * 8;

        for (int i = tid; i < Npad; i += SEL_BLOCK) {
            bool valid = (i < N);
            unsigned long long key = valid ? make_key(A, i, col, neg) : 0ull;
            valid = valid && ((key & hmask) == pref);
            unsigned bucket = valid ? (unsigned)((key >> shift) & 255u) : 0x100u;
            unsigned mm = __match_any_sync(0xFFFFFFFFu, bucket);
            if (valid && lane == (__ffs(mm) - 1))
                atomicAdd(&hist[bucket], __popc(mm));
        }
        __syncthreads();

        if (tid == 0) {
            int k = s_k;
            for (int bb = 255; bb >= 0; --bb) {
                int c = (int)hist[bb];
                if (k <= c) {
                    s_pref = pref | ((unsigned long long)(unsigned)bb << shift);
                    break;
                }
                k -= c;
            }
            s_k = k;
        }
        __syncthreads();
    }

    const unsigned long long T = s_pref;   // exact K-th largest key (keys unique)

    // ---- compact the exactly-K keys >= T into shared ----
    if (tid == 0) s_cnt = 0;
    keys[tid] = 0ull;
    keys[tid + SEL_BLOCK] = 0ull;
    __syncthreads();

    for (int i = tid; i < N; i += SEL_BLOCK) {
        unsigned long long key = make_key(A, i, col, neg);
        if (key >= T) {
            int p = atomicAdd(&s_cnt, 1);
            if (p < SORT_M) keys[p] = key;
        }
    }
    __syncthreads();

    // ---- bitonic sort ascending, SORT_M elems, SEL_BLOCK threads (1 pair each) ----
    for (unsigned size = 2; size <= SORT_M; size <<= 1) {
        for (unsigned stride = size >> 1; stride > 0; stride >>= 1) {
            __syncthreads();
            unsigned lo = tid & (stride - 1);
            unsigned i  = ((unsigned)(tid - lo) << 1) | lo;
            unsigned j  = i + stride;
            bool up = ((i & size) == 0);
            unsigned long long a = keys[i], c = keys[j];
            if (up ? (a > c) : (a < c)) { keys[i] = c; keys[j] = a; }
        }
    }
    __syncthreads();

    // top-K descending = keys[SORT_M-1 - j]
    for (int j = tid; j < K; j += SEL_BLOCK) {
        unsigned long long key = keys[SORT_M - 1 - j];
        g_idx[sel * K + j] = (int)(~(unsigned)(key & 0xFFFFFFFFull));
    }
}

// One warp per output row: gather h[idx], dual dot with W (shared), softmax(2).
__global__ void gemv_softmax_kernel(const float* __restrict__ h,
                                    const float* __restrict__ W,
                                    const float* __restrict__ b,
                                    float* __restrict__ out,
                                    int D, int K) {
    extern __shared__ float ws[];   // D*2 floats, layout W[d*2+c]
    const int tid = threadIdx.x;
    for (int j = tid; j < D * 2; j += blockDim.x) ws[j] = W[j];
    __syncthreads();

    const int warp = tid >> 5, lane = tid & 31;
    const int r = blockIdx.x * (blockDim.x >> 5) + warp;
    const int total = 3 * K;
    if (r >= total) return;

    const int idx = g_idx[r];
    const float4* hp = (const float4*)(h + (size_t)idx * D);

    float s0 = 0.f, s1 = 0.f;
    const int nq = D >> 2;
    for (int t = lane; t < nq; t += 32) {
        float4 v = hp[t];
        int j = t << 2;
        s0 = fmaf(v.x, ws[j * 2 + 0], s0);
        s1 = fmaf(v.x, ws[j * 2 + 1], s1);
        s0 = fmaf(v.y, ws[j * 2 + 2], s0);
        s1 = fmaf(v.y, ws[j * 2 + 3], s1);
        s0 = fmaf(v.z, ws[j * 2 + 4], s0);
        s1 = fmaf(v.z, ws[j * 2 + 5], s1);
        s0 = fmaf(v.w, ws[j * 2 + 6], s0);
        s1 = fmaf(v.w, ws[j * 2 + 7], s1);
    }
    #pragma unroll
    for (int o = 16; o; o >>= 1) {
        s0 += __shfl_down_sync(0xFFFFFFFFu, s0, o);
        s1 += __shfl_down_sync(0xFFFFFFFFu, s1, o);
    }

    if (lane == 0) {
        float z0 = s0 + b[0], z1 = s1 + b[1];
        float m  = fmaxf(z0, z1);
        float e0 = expf(z0 - m), e1 = expf(z1 - m);
        float inv = 1.0f / (e0 + e1);
        out[r] = (r < K) ? 1.0f : 0.0f;                    // labels
        out[3 * K + r * 2 + 0] = z0;                       // logits_unnorm
        out[3 * K + r * 2 + 1] = z1;
        out[9 * K + r * 2 + 0] = e0 * inv;                 // softmax
        out[9 * K + r * 2 + 1] = e1 * inv;
    }
}

extern "C" void kernel_launch(void* const* d_in, const int* in_sizes, int n_in,
                              void* d_out, int out_size) {
    const float* h = (const float*)d_in[0];   // (N,1,D)
    const float* A = (const float*)d_in[1];   // (N,1,2)
    const float* W = (const float*)d_in[2];   // (D,2)
    const float* b = (const float*)d_in[3];   // (2,)
    const int* bag = (n_in > 4) ? (const int*)d_in[4] : nullptr;

    const int N = in_sizes[1] / 2;
    const int D = in_sizes[0] / N;
    int K = (int)(0.02 * (double)N);
    if (K == 0) K = 8;
    if (K > SORT_M) K = SORT_M;

    select_topk_kernel<<<3, SEL_BLOCK>>>(A, bag, N, K);

    const int rows = 3 * K;
    const int threads = 256;                        // 8 warps -> 8 rows/block
    const int blocks = (rows + 7) / 8;
    const size_t smem = (size_t)(D * 2) * sizeof(float);
    gemv_softmax_kernel<<<blocks, threads, smem>>>(h, W, b, (float*)d_out, D, K);
}

// round 2
// speedup vs baseline: 3.5548x; 3.5548x over previous
#include <cuda_runtime.h>
#include <cuda_bf16.h>
#include <math.h>

// ---------------------------------------------------------------------------
// 3x exact top-K over columns of A (N x 2): (value desc, index asc) like
// lax.top_k. Two-phase chip-wide selection:
//   Z: zero histograms/counters
//   H: 16384-bin histogram of fkey>>18 for all 3 selections (chip-wide)
//   P: per-selection: find threshold bin (suffix-sum over bins)
//   C: compact candidates (fkey >= bin low) as 64-bit keys (chip-wide)
//   S: per-selection bitonic sort of <=4096 candidates, emit top-K indices
//   G: gather h rows, 512->2 GEMV (W in smem), softmax(2), write outputs
// Output (float32, 15K): [0,3K) labels | [3K,9K) logits | [9K,15K) softmax
// ---------------------------------------------------------------------------

#define NBINS   16384
#define CAP     4096      // candidate capacity (pow2, >= K + max bin count)
#define KMAX    2048

__device__ unsigned            g_hist[3][NBINS];
__device__ unsigned            g_binlo[3];
__device__ int                 g_cnt[3];
__device__ unsigned long long  g_cand[3][CAP];
__device__ int                 g_idx[3 * KMAX];

__device__ __forceinline__ unsigned fkey(float f) {
    unsigned u = __float_as_uint(f);
    return (u & 0x80000000u) ? ~u : (u | 0x80000000u);   // monotonic
}

__device__ __forceinline__ void agg_add(unsigned* hist, unsigned bin) {
    unsigned act = __activemask();
    unsigned mm  = __match_any_sync(act, bin);
    if ((__ffs(mm) - 1) == (int)(threadIdx.x & 31))
        atomicAdd(&hist[bin], __popc(mm));
}

// ---- Z: zero state -------------------------------------------------------
__global__ void zero_kernel() {
    int t = blockIdx.x * blockDim.x + threadIdx.x;
    int total = 3 * NBINS;
    for (int i = t; i < total; i += gridDim.x * blockDim.x)
        ((unsigned*)g_hist)[i] = 0u;
    if (t < 3) g_cnt[t] = 0;
}

// ---- H: chip-wide histogram (all 3 selections) ----------------------------
__global__ void hist_kernel(const float2* __restrict__ A2,
                            const int* __restrict__ bag, int N) {
    int bg = bag ? *bag : 1;
    int t = blockIdx.x * blockDim.x + threadIdx.x;
    int stride = gridDim.x * blockDim.x;
    for (int i = t; i < N; i += stride) {
        float2 a = A2[i];
        float v  = bg ? a.y : a.x;     // A[:, bag]
        float vo = bg ? a.x : a.y;     // A[:, 1-bag]
        agg_add(g_hist[0], fkey(v)   >> 18);
        agg_add(g_hist[1], fkey(-v)  >> 18);
        agg_add(g_hist[2], fkey(vo)  >> 18);
    }
}

// ---- P: find threshold bin per selection (1 block each) -------------------
__global__ __launch_bounds__(1024)
void pick_kernel(int K) {
    const int sel = blockIdx.x, tid = threadIdx.x;
    const unsigned* hist = g_hist[sel];
    __shared__ unsigned s[1024];

    // thread t covers 16 bins descending: bins [NBINS-1 - t*16 .. -15]
    unsigned part = 0;
    #pragma unroll
    for (int j = 0; j < 16; j++) part += hist[NBINS - 1 - (tid * 16 + j)];
    s[tid] = part;
    __syncthreads();
    // inclusive scan (Hillis-Steele)
    for (int off = 1; off < 1024; off <<= 1) {
        unsigned v = (tid >= off) ? s[tid - off] : 0u;
        __syncthreads();
        s[tid] += v;
        __syncthreads();
    }
    unsigned cum = s[tid];
    unsigned before = cum - part;
    if (before < (unsigned)K && cum >= (unsigned)K) {
        int kk = K - (int)before;
        for (int j = 0; j < 16; j++) {
            int b = NBINS - 1 - (tid * 16 + j);
            kk -= (int)hist[b];
            if (kk <= 0) { g_binlo[sel] = (unsigned)b; break; }
        }
    }
}

// ---- C: chip-wide candidate compaction ------------------------------------
__global__ void compact_kernel(const float2* __restrict__ A2,
                               const int* __restrict__ bag, int N) {
    int bg = bag ? *bag : 1;
    unsigned lo0 = g_binlo[0] << 18;
    unsigned lo1 = g_binlo[1] << 18;
    unsigned lo2 = g_binlo[2] << 18;
    int t = blockIdx.x * blockDim.x + threadIdx.x;
    int stride = gridDim.x * blockDim.x;
    for (int i = t; i < N; i += stride) {
        float2 a = A2[i];
        float v  = bg ? a.y : a.x;
        float vo = bg ? a.x : a.y;
        unsigned k0 = fkey(v), k1 = fkey(-v), k2 = fkey(vo);
        unsigned long long il = (unsigned)(~(unsigned)i);
        if (k0 >= lo0) {
            int p = atomicAdd(&g_cnt[0], 1);
            if (p < CAP) g_cand[0][p] = ((unsigned long long)k0 << 32) | il;
        }
        if (k1 >= lo1) {
            int p = atomicAdd(&g_cnt[1], 1);
            if (p < CAP) g_cand[1][p] = ((unsigned long long)k1 << 32) | il;
        }
        if (k2 >= lo2) {
            int p = atomicAdd(&g_cnt[2], 1);
            if (p < CAP) g_cand[2][p] = ((unsigned long long)k2 << 32) | il;
        }
    }
}

// ---- S: per-selection bitonic sort of CAP keys, emit top-K indices --------
__global__ __launch_bounds__(1024)
void sort_kernel(int K) {
    const int sel = blockIdx.x, tid = threadIdx.x;
    __shared__ unsigned long long keys[CAP];

    int cnt = g_cnt[sel]; if (cnt > CAP) cnt = CAP;
    for (int j = tid; j < CAP; j += 1024)
        keys[j] = (j < cnt) ? g_cand[sel][j] : 0ull;
    __syncthreads();

    // bitonic sort ascending
    for (unsigned size = 2; size <= CAP; size <<= 1) {
        for (unsigned stride = size >> 1; stride > 0; stride >>= 1) {
            for (int p = tid; p < CAP / 2; p += 1024) {
                unsigned lo = p & (stride - 1);
                unsigned i  = ((unsigned)(p - lo) << 1) | lo;
                unsigned j  = i + stride;
                bool up = ((i & size) == 0);
                unsigned long long a = keys[i], c = keys[j];
                if (up ? (a > c) : (a < c)) { keys[i] = c; keys[j] = a; }
            }
            __syncthreads();
        }
    }

    for (int j = tid; j < K; j += 1024) {
        unsigned long long key = keys[CAP - 1 - j];
        g_idx[sel * K + j] = (int)(~(unsigned)(key & 0xFFFFFFFFull));
    }
}

// ---- G: gather + GEMV(512->2) + softmax; 2 rows per warp for MLP ----------
__global__ void gemv_softmax_kernel(const float* __restrict__ h,
                                    const float* __restrict__ W,
                                    const float* __restrict__ b,
                                    float* __restrict__ out,
                                    int D, int K) {
    extern __shared__ float ws[];   // D*2 floats, W[d*2+c]
    const int tid = threadIdx.x;
    for (int j = tid; j < D * 2; j += blockDim.x) ws[j] = W[j];
    __syncthreads();

    const int warp = tid >> 5, lane = tid & 31;
    const int rbase = (blockIdx.x * (blockDim.x >> 5) + warp) * 2;
    const int total = 3 * K;
    if (rbase >= total) return;

    const bool two = (rbase + 1 < total);
    const int ia = g_idx[rbase];
    const int ib = two ? g_idx[rbase + 1] : ia;
    const float4* pa = (const float4*)(h + (size_t)ia * D);
    const float4* pb = (const float4*)(h + (size_t)ib * D);

    float a0 = 0.f, a1 = 0.f, b0 = 0.f, b1 = 0.f;
    const int nq = D >> 2;
    for (int t = lane; t < nq; t += 32) {
        float4 va = pa[t];
        float4 vb = pb[t];
        int j = t << 3;  // t*4*2
        a0 = fmaf(va.x, ws[j + 0], a0);  a1 = fmaf(va.x, ws[j + 1], a1);
        b0 = fmaf(vb.x, ws[j + 0], b0);  b1 = fmaf(vb.x, ws[j + 1], b1);
        a0 = fmaf(va.y, ws[j + 2], a0);  a1 = fmaf(va.y, ws[j + 3], a1);
        b0 = fmaf(vb.y, ws[j + 2], b0);  b1 = fmaf(vb.y, ws[j + 3], b1);
        a0 = fmaf(va.z, ws[j + 4], a0);  a1 = fmaf(va.z, ws[j + 5], a1);
        b0 = fmaf(vb.z, ws[j + 4], b0);  b1 = fmaf(vb.z, ws[j + 5], b1);
        a0 = fmaf(va.w, ws[j + 6], a0);  a1 = fmaf(va.w, ws[j + 7], a1);
        b0 = fmaf(vb.w, ws[j + 6], b0);  b1 = fmaf(vb.w, ws[j + 7], b1);
    }
    #pragma unroll
    for (int o = 16; o; o >>= 1) {
        a0 += __shfl_down_sync(0xFFFFFFFFu, a0, o);
        a1 += __shfl_down_sync(0xFFFFFFFFu, a1, o);
        b0 += __shfl_down_sync(0xFFFFFFFFu, b0, o);
        b1 += __shfl_down_sync(0xFFFFFFFFu, b1, o);
    }

    if (lane == 0) {
        float bb0 = b[0], bb1 = b[1];
        {
            int r = rbase;
            float z0 = a0 + bb0, z1 = a1 + bb1;
            float m = fmaxf(z0, z1);
            float e0 = expf(z0 - m), e1 = expf(z1 - m);
            float inv = 1.0f / (e0 + e1);
            out[r] = (r < K) ? 1.0f : 0.0f;
            out[3 * K + r * 2 + 0] = z0;
            out[3 * K + r * 2 + 1] = z1;
            out[9 * K + r * 2 + 0] = e0 * inv;
            out[9 * K + r * 2 + 1] = e1 * inv;
        }
        if (two) {
            int r = rbase + 1;
            float z0 = b0 + bb0, z1 = b1 + bb1;
            float m = fmaxf(z0, z1);
            float e0 = expf(z0 - m), e1 = expf(z1 - m);
            float inv = 1.0f / (e0 + e1);
            out[r] = (r < K) ? 1.0f : 0.0f;
            out[3 * K + r * 2 + 0] = z0;
            out[3 * K + r * 2 + 1] = z1;
            out[9 * K + r * 2 + 0] = e0 * inv;
            out[9 * K + r * 2 + 1] = e1 * inv;
        }
    }
}

extern "C" void kernel_launch(void* const* d_in, const int* in_sizes, int n_in,
                              void* d_out, int out_size) {
    const float* h = (const float*)d_in[0];   // (N,1,D)
    const float* A = (const float*)d_in[1];   // (N,1,2)
    const float* W = (const float*)d_in[2];   // (D,2)
    const float* b = (const float*)d_in[3];   // (2,)
    const int* bag = (n_in > 4) ? (const int*)d_in[4] : nullptr;

    const int N = in_sizes[1] / 2;
    const int D = in_sizes[0] / N;
    int K = (int)(0.02 * (double)N);
    if (K == 0) K = 8;
    if (K > KMAX) K = KMAX;

    const float2* A2 = (const float2*)A;

    zero_kernel<<<48, 1024>>>();
    hist_kernel<<<128, 256>>>(A2, bag, N);
    pick_kernel<<<3, 1024>>>(K);
    compact_kernel<<<128, 256>>>(A2, bag, N);
    sort_kernel<<<3, 1024>>>(K);

    const int rows = 3 * K;
    const int threads = 256;                  // 8 warps x 2 rows = 16 rows/block
    const int blocks = (rows + 15) / 16;
    const size_t smem = (size_t)(D * 2) * sizeof(float);
    gemv_softmax_kernel<<<blocks, threads, smem>>>(h, W, b, (float*)d_out, D, K);
}